// round 17
// baseline (speedup 1.0000x reference)
#include <cuda_runtime.h>
#include <cuda_fp16.h>
#include <cstdint>
#include <cstddef>

// Problem constants (fixed by the reference)
#define BB   2
#define SS   2048
#define HH   2048
#define NHH  16
#define HDD  128
#define MM   (BB * SS)   // 4096 rows

#define QSCALE 0.08838834764831845f   // 1/sqrt(128)

// ---------------------------------------------------------------------------
// Scratch (allocation-free rule: __device__ globals)
// ---------------------------------------------------------------------------
__device__ __half g_q[(size_t)BB * NHH * SS * HDD];   // [B,NH,S,HD] (pre-scaled)
__device__ __half g_k[(size_t)BB * NHH * SS * HDD];
__device__ __half g_v[(size_t)BB * NHH * SS * HDD];
__device__ __half g_att[(size_t)MM * HH];             // [B,S,H]
__device__ __half g_hidt[(size_t)MM * HH];            // hidden, fp16
__device__ __half g_wt[(size_t)3 * HH * HH];          // Wq,Wk,Wv concat (fp16)
__device__ __half g_wo[(size_t)HH * HH];              // Wo fp16

// ---------------------------------------------------------------------------
// Helpers
// ---------------------------------------------------------------------------
__device__ __forceinline__ void mma_f16(float c[4], const uint32_t a[4],
                                        const uint32_t b[2]) {
    asm volatile(
        "mma.sync.aligned.m16n8k16.row.col.f32.f16.f16.f32 "
        "{%0,%1,%2,%3}, {%4,%5,%6,%7}, {%8,%9}, {%0,%1,%2,%3};\n"
        : "+f"(c[0]), "+f"(c[1]), "+f"(c[2]), "+f"(c[3])
        : "r"(a[0]), "r"(a[1]), "r"(a[2]), "r"(a[3]), "r"(b[0]), "r"(b[1]));
}

__device__ __forceinline__ void cp_async16(uint32_t s, const void* g) {
    asm volatile("cp.async.cg.shared.global [%0], [%1], 16;\n" :: "r"(s), "l"(g));
}

__device__ __forceinline__ uint32_t smem_u32(const void* p) {
    return (uint32_t)__cvta_generic_to_shared(p);
}

__device__ __forceinline__ void ldmx4(uint32_t& r0, uint32_t& r1,
                                      uint32_t& r2, uint32_t& r3, uint32_t a) {
    asm volatile(
        "ldmatrix.sync.aligned.m8n8.x4.shared.b16 {%0,%1,%2,%3}, [%4];"
        : "=r"(r0), "=r"(r1), "=r"(r2), "=r"(r3) : "r"(a));
}

__device__ __forceinline__ void ldmx4t(uint32_t& r0, uint32_t& r1,
                                       uint32_t& r2, uint32_t& r3, uint32_t a) {
    asm volatile(
        "ldmatrix.sync.aligned.m8n8.x4.trans.shared.b16 {%0,%1,%2,%3}, [%4];"
        : "=r"(r0), "=r"(r1), "=r"(r2), "=r"(r3) : "r"(a));
}

__device__ __forceinline__ uint32_t packh2(float a, float b) {
    __half2 h = __floats2half2_rn(a, b);
    return *(uint32_t*)&h;
}

// ---------------------------------------------------------------------------
// Pre-convert: fp32 -> fp16 (rn), vectorized
// ---------------------------------------------------------------------------
__global__ __launch_bounds__(256) void cvt_f2h(const float* __restrict__ in,
                                               __half* __restrict__ out, int n4)
{
    int i = blockIdx.x * 256 + threadIdx.x;
    if (i < n4) {
        float4 v = ((const float4*)in)[i];
        __half2* o = (__half2*)(out + (size_t)i * 4);
        o[0] = __floats2half2_rn(v.x, v.y);
        o[1] = __floats2half2_rn(v.z, v.w);
    }
}

// ---------------------------------------------------------------------------
// Fused QKV GEMM, N-tile 96 (wave-quantization fix: 2048 CTAs -> 7 waves).
// Block 128x96, BK=64 halves, 3-stage cp.async, one sync per K-tile.
// 8 warps as 4m x 2n; warp tile 32x48 (2 x 6 mma tiles).
// Per-COLUMN q/k/v select in epilogue (96 ∤ 2048 boundaries; pairs are even
// so a half2 never straddles). Q output pre-scaled by 1/sqrt(HD).
// ---------------------------------------------------------------------------
#define GROW_B   144                 // bytes per smem row (72 halves)
#define GROW_W   36                  // words per smem row
#define QA_TILE_B (128 * GROW_B)     // 18432
#define QB_TILE_B (96 * GROW_B)      // 13824
#define QSTG_B   (QA_TILE_B + QB_TILE_B)   // 32256
#define QKV_SMEM (512 + 3 * QSTG_B)  // 97280

__global__ __launch_bounds__(256, 2) void gemm_qkv96(
    const __half* __restrict__ A, const __half* __restrict__ W,
    const float* __restrict__ b0, const float* __restrict__ b1,
    const float* __restrict__ b2,
    __half* __restrict__ o0, __half* __restrict__ o1, __half* __restrict__ o2)
{
    extern __shared__ char smc[];
    const uint32_t smem_base = smem_u32(smc);

    const int tid  = threadIdx.x;
    const int lane = tid & 31;
    const int warp = tid >> 5;
    const int wm   = (warp >> 1) * 32;   // 0,32,64,96
    const int wn   = (warp & 1) * 48;    // 0,48

    const int m0  = blockIdx.y * 128;
    const int n0g = blockIdx.x * 96;     // 0..6048 across concat q|k|v

    const int lrow = tid >> 1;           // 0..127
    const int lch0 = (tid & 1) * 4;      // 16B chunk base 0 or 4

    const __half* Ag = A + (size_t)(m0 + lrow) * HH;
    const __half* Wg = W + (size_t)(n0g + lrow) * HH;  // valid for lrow<96

    auto load_tile = [&](int stage, int k0 /*halves*/) {
        const uint32_t sa = smem_base + 512 + stage * QSTG_B + lrow * GROW_B;
        const uint32_t sb = smem_base + 512 + stage * QSTG_B + QA_TILE_B + lrow * GROW_B;
#pragma unroll
        for (int c = 0; c < 4; c++) {
            const int ch = lch0 + c;                 // 0..7
            cp_async16(sa + ch * 16, Ag + k0 + ch * 8);
            if (lrow < 96)
                cp_async16(sb + ch * 16, Wg + k0 + ch * 8);
        }
        asm volatile("cp.async.commit_group;\n");
    };

    float acc[2][6][4];
#pragma unroll
    for (int i = 0; i < 2; i++)
#pragma unroll
        for (int j = 0; j < 6; j++)
#pragma unroll
            for (int t = 0; t < 4; t++) acc[i][j][t] = 0.0f;

    const int ntiles = HH / 64;          // 32
    load_tile(0, 0);
    load_tile(1, 64);

    for (int kt = 0; kt < ntiles; kt++) {
        if (kt + 1 < ntiles) asm volatile("cp.async.wait_group 1;\n");
        else                 asm volatile("cp.async.wait_group 0;\n");
        __syncthreads();

        if (kt + 2 < ntiles) load_tile((kt + 2) % 3, (kt + 2) * 64);

        const uint32_t* As = (const uint32_t*)(smc + 512 + (kt % 3) * QSTG_B);
        const uint32_t* Bs = (const uint32_t*)(smc + 512 + (kt % 3) * QSTG_B + QA_TILE_B);

#pragma unroll
        for (int ks = 0; ks < 4; ks++) {
            const int kk = ks * 8 + (lane & 3);
            uint32_t afr[2][4], bfr[6][2];
#pragma unroll
            for (int i = 0; i < 2; i++) {
                const int r = wm + i * 16 + (lane >> 2);
                afr[i][0] = As[r * GROW_W + kk];
                afr[i][1] = As[(r + 8) * GROW_W + kk];
                afr[i][2] = As[r * GROW_W + kk + 4];
                afr[i][3] = As[(r + 8) * GROW_W + kk + 4];
            }
#pragma unroll
            for (int j = 0; j < 6; j++) {
                const int n = wn + j * 8 + (lane >> 2);
                bfr[j][0] = Bs[n * GROW_W + kk];
                bfr[j][1] = Bs[n * GROW_W + kk + 4];
            }
#pragma unroll
            for (int i = 0; i < 2; i++)
#pragma unroll
                for (int j = 0; j < 6; j++)
                    mma_f16(acc[i][j], afr[i], bfr[j]);
        }
    }

    // Epilogue: per-column-pair q/k/v select; Q pre-scaled by QSCALE
#pragma unroll
    for (int i = 0; i < 2; i++) {
        const int r = wm + i * 16 + (lane >> 2);
#pragma unroll
        for (int j = 0; j < 6; j++) {
            const int cc = wn + j * 8 + (lane & 3) * 2;
            const int n  = n0g + cc;               // global concat col (even)
            const int sel  = n >> 11;              // 0:q 1:k 2:v (pair same sel)
            const int nl   = n & 2047;
            const float* bp = (sel == 0) ? b0 : (sel == 1) ? b1 : b2;
            __half* Ch      = (sel == 0) ? o0 : (sel == 1) ? o1 : o2;
            const float sc  = (sel == 0) ? QSCALE : 1.0f;
            const float bv0 = bp[nl], bv1 = bp[nl + 1];
            const int hidx = nl >> 7, d = nl & 127;      // HD = 128
#pragma unroll
            for (int hh = 0; hh < 2; hh++) {
                const int m = m0 + r + hh * 8;
                const float v0 = (acc[i][j][hh * 2 + 0] + bv0) * sc;
                const float v1 = (acc[i][j][hh * 2 + 1] + bv1) * sc;
                const int b = m / SS, s = m % SS;
                __half2* dst = (__half2*)(Ch +
                    (((size_t)(b * NHH + hidx)) * SS + s) * HDD + d);
                *dst = __floats2half2_rn(v0, v1);
            }
        }
    }
}

// ---------------------------------------------------------------------------
// Output projection GEMM (proven R14 body, MODE 0 only): out = att @ Wo^T + bo
// Block 128x128, BK=64, 3-stage cp.async, one sync per K-tile. fp32 output.
// ---------------------------------------------------------------------------
#define GTILE_B  (128 * GROW_B)      // 18432
#define GSTG_B   (2 * GTILE_B)       // 36864
#define GEMM_SMEM (512 + 3 * GSTG_B) // 111104

__global__ __launch_bounds__(256, 2) void gemm_proj(
    const __half* __restrict__ A, const __half* __restrict__ W,
    const float* __restrict__ bias, float* __restrict__ Cf)
{
    extern __shared__ char smc[];
    const uint32_t smem_base = smem_u32(smc);
    float* bias_s = (float*)smc;

    const int tid  = threadIdx.x;
    const int lane = tid & 31;
    const int warp = tid >> 5;
    const int wm   = (warp >> 1) * 32;
    const int wn   = (warp & 1) * 64;

    const int m0 = blockIdx.y * 128;
    const int n0 = blockIdx.x * 128;

    if (tid < 128) bias_s[tid] = bias[n0 + tid];

    const int lrow = tid >> 1;
    const int lch0 = (tid & 1) * 4;

    const __half* Ag = A + (size_t)(m0 + lrow) * HH;
    const __half* Wg = W + (size_t)(n0 + lrow) * HH;

    auto load_tile = [&](int stage, int k0) {
        const uint32_t sa = smem_base + 512 + stage * GSTG_B + lrow * GROW_B;
        const uint32_t sb = sa + GTILE_B;
#pragma unroll
        for (int c = 0; c < 4; c++) {
            const int ch = lch0 + c;
            cp_async16(sa + ch * 16, Ag + k0 + ch * 8);
            cp_async16(sb + ch * 16, Wg + k0 + ch * 8);
        }
        asm volatile("cp.async.commit_group;\n");
    };

    float acc[2][8][4];
#pragma unroll
    for (int i = 0; i < 2; i++)
#pragma unroll
        for (int j = 0; j < 8; j++)
#pragma unroll
            for (int t = 0; t < 4; t++) acc[i][j][t] = 0.0f;

    const int ntiles = HH / 64;
    load_tile(0, 0);
    load_tile(1, 64);

    for (int kt = 0; kt < ntiles; kt++) {
        if (kt + 1 < ntiles) asm volatile("cp.async.wait_group 1;\n");
        else                 asm volatile("cp.async.wait_group 0;\n");
        __syncthreads();

        if (kt + 2 < ntiles) load_tile((kt + 2) % 3, (kt + 2) * 64);

        const uint32_t* As = (const uint32_t*)(smc + 512 + (kt % 3) * GSTG_B);
        const uint32_t* Bs = As + GTILE_B / 4;

#pragma unroll
        for (int ks = 0; ks < 4; ks++) {
            const int kk = ks * 8 + (lane & 3);
            uint32_t afr[2][4], bfr[8][2];
#pragma unroll
            for (int i = 0; i < 2; i++) {
                const int r = wm + i * 16 + (lane >> 2);
                afr[i][0] = As[r * GROW_W + kk];
                afr[i][1] = As[(r + 8) * GROW_W + kk];
                afr[i][2] = As[r * GROW_W + kk + 4];
                afr[i][3] = As[(r + 8) * GROW_W + kk + 4];
            }
#pragma unroll
            for (int j = 0; j < 8; j++) {
                const int n = wn + j * 8 + (lane >> 2);
                bfr[j][0] = Bs[n * GROW_W + kk];
                bfr[j][1] = Bs[n * GROW_W + kk + 4];
            }
#pragma unroll
            for (int i = 0; i < 2; i++)
#pragma unroll
                for (int j = 0; j < 8; j++)
                    mma_f16(acc[i][j], afr[i], bfr[j]);
        }
    }

#pragma unroll
    for (int i = 0; i < 2; i++) {
        const int r = wm + i * 16 + (lane >> 2);
#pragma unroll
        for (int j = 0; j < 8; j++) {
            const int cc = wn + j * 8 + (lane & 3) * 2;
#pragma unroll
            for (int hh = 0; hh < 2; hh++) {
                const int m = m0 + r + hh * 8;
                const float v0 = acc[i][j][hh * 2 + 0] + bias_s[cc];
                const float v1 = acc[i][j][hh * 2 + 1] + bias_s[cc + 1];
                *(float2*)(Cf + (size_t)m * HH + n0 + cc) = make_float2(v0, v1);
            }
        }
    }
}

// ---------------------------------------------------------------------------
// FA2-style fp16 flash attention (proven R15 kernel; Q pre-scaled upstream,
// so the per-block scale loop is removed).
// Grid: (16, NH, B); 256 threads = 8 warps; warp owns 16 q-rows.
// ---------------------------------------------------------------------------
#define FROW_B   272                  // bytes per smem row (136 halves)
#define FOFF_Q   0                    // 128 * 272 = 34816
#define FOFF_K   34816                // + s*17408
#define FOFF_V   69632                // + s*17408
#define FLASH_SMEM 104448

__global__ __launch_bounds__(256, 1) void flash_attn_f16(
    const __half* __restrict__ Q, const __half* __restrict__ K,
    const __half* __restrict__ V, __half* __restrict__ Out)
{
    extern __shared__ char smc[];
    const uint32_t sb = smem_u32(smc);

    const int tid  = threadIdx.x;
    const int lane = tid & 31;
    const int warp = tid >> 5;

    const int qi = 15 - blockIdx.x;      // longest CTAs launch first
    const int h  = blockIdx.y;
    const int b  = blockIdx.z;
    const int q0 = qi * 128;

    const size_t head_base = ((size_t)(b * NHH + h)) * SS * HDD;
    const __half* Qg = Q + head_base + (size_t)q0 * HDD;
    const __half* Kg = K + head_base;
    const __half* Vg = V + head_base;

    // ---- stage Q (128 rows x 256 B = 2048 16B chunks) ----
#pragma unroll
    for (int t = 0; t < 8; t++) {
        const int idx = tid + t * 256;        // 0..2047
        const int r = idx >> 4, ch = idx & 15;
        *(uint4*)(smc + FOFF_Q + r * FROW_B + ch * 16) =
            *(const uint4*)(Qg + (size_t)r * HDD + ch * 8);
    }
    __syncthreads();

    const uint32_t lm_row = (uint32_t)(lane & 15);
    const uint32_t lm_chb = (uint32_t)((lane >> 4) * 16);

    uint32_t qf[8][4];
    {
        const uint32_t qbase = sb + FOFF_Q + (warp * 16 + lm_row) * FROW_B + lm_chb;
#pragma unroll
        for (int kc = 0; kc < 8; kc++)
            ldmx4(qf[kc][0], qf[kc][1], qf[kc][2], qf[kc][3], qbase + kc * 32);
    }

    float o[16][4];
#pragma unroll
    for (int j = 0; j < 16; j++)
#pragma unroll
        for (int t = 0; t < 4; t++) o[j][t] = 0.0f;
    float m0 = -1e30f, m1 = -1e30f, l0 = 0.0f, l1 = 0.0f;

    const int nkb = 2 * (qi + 1);
    const int wr0 = q0 + warp * 16;           // warp's min global q row
    const int rg0 = wr0 + (lane >> 2);        // this thread's rows
    const int rg1 = rg0 + 8;

    auto load_kv = [&](int stage, int kb) {
        const int k0 = kb * 64;
        const uint32_t kbase = sb + FOFF_K + stage * 17408;
        const uint32_t vbase = sb + FOFF_V + stage * 17408;
#pragma unroll
        for (int t = 0; t < 4; t++) {
            const int idx = tid + t * 256;    // 0..1023
            const int r = idx >> 4, ch = idx & 15;
            cp_async16(kbase + r * FROW_B + ch * 16,
                       Kg + (size_t)(k0 + r) * HDD + ch * 8);
            cp_async16(vbase + r * FROW_B + ch * 16,
                       Vg + (size_t)(k0 + r) * HDD + ch * 8);
        }
        asm volatile("cp.async.commit_group;\n");
    };

    load_kv(0, 0);

    for (int kb = 0; kb < nkb; kb++) {
        const int s  = kb & 1;
        const int k0 = kb * 64;

        asm volatile("cp.async.wait_group 0;\n");
        __syncthreads();                       // load done + prev compute done
        if (kb + 1 < nkb) load_kv(s ^ 1, kb + 1);

        if (k0 <= wr0 + 15) {                  // not fully above diagonal
            // ---- S = Q @ K^T (16 x 64 per warp); Q pre-scaled ----
            float sv[8][4];
#pragma unroll
            for (int j = 0; j < 8; j++)
#pragma unroll
                for (int t = 0; t < 4; t++) sv[j][t] = 0.0f;

            const uint32_t kbase = sb + FOFF_K + s * 17408 + lm_row * FROW_B + lm_chb;
#pragma unroll
            for (int kc = 0; kc < 8; kc++) {
#pragma unroll
                for (int np = 0; np < 4; np++) {
                    uint32_t r0, r1, r2, r3;
                    ldmx4(r0, r1, r2, r3, kbase + np * 16 * FROW_B + kc * 32);
                    uint32_t bb0[2] = {r0, r2};
                    uint32_t bb1[2] = {r1, r3};
                    mma_f16(sv[2 * np],     qf[kc], bb0);
                    mma_f16(sv[2 * np + 1], qf[kc], bb1);
                }
            }

            // causal mask
            if (k0 + 63 > wr0) {
#pragma unroll
                for (int j = 0; j < 8; j++) {
                    const int cg = k0 + j * 8 + (lane & 3) * 2;
                    if (cg     > rg0) sv[j][0] = -1e30f;
                    if (cg + 1 > rg0) sv[j][1] = -1e30f;
                    if (cg     > rg1) sv[j][2] = -1e30f;
                    if (cg + 1 > rg1) sv[j][3] = -1e30f;
                }
            }

            // ---- online softmax in registers (quad reduction) ----
            float mx0 = -1e30f, mx1 = -1e30f;
#pragma unroll
            for (int j = 0; j < 8; j++) {
                mx0 = fmaxf(mx0, fmaxf(sv[j][0], sv[j][1]));
                mx1 = fmaxf(mx1, fmaxf(sv[j][2], sv[j][3]));
            }
            mx0 = fmaxf(mx0, __shfl_xor_sync(0xffffffffu, mx0, 1));
            mx0 = fmaxf(mx0, __shfl_xor_sync(0xffffffffu, mx0, 2));
            mx1 = fmaxf(mx1, __shfl_xor_sync(0xffffffffu, mx1, 1));
            mx1 = fmaxf(mx1, __shfl_xor_sync(0xffffffffu, mx1, 2));

            const float mn0 = fmaxf(m0, mx0);
            const float mn1 = fmaxf(m1, mx1);
            const float corr0 = __expf(m0 - mn0);
            const float corr1 = __expf(m1 - mn1);
            m0 = mn0; m1 = mn1;

            float sum0 = 0.0f, sum1 = 0.0f;
#pragma unroll
            for (int j = 0; j < 8; j++) {
                sv[j][0] = __expf(sv[j][0] - mn0);
                sv[j][1] = __expf(sv[j][1] - mn0);
                sv[j][2] = __expf(sv[j][2] - mn1);
                sv[j][3] = __expf(sv[j][3] - mn1);
                sum0 += sv[j][0] + sv[j][1];
                sum1 += sv[j][2] + sv[j][3];
            }
            sum0 += __shfl_xor_sync(0xffffffffu, sum0, 1);
            sum0 += __shfl_xor_sync(0xffffffffu, sum0, 2);
            sum1 += __shfl_xor_sync(0xffffffffu, sum1, 1);
            sum1 += __shfl_xor_sync(0xffffffffu, sum1, 2);
            l0 = l0 * corr0 + sum0;
            l1 = l1 * corr1 + sum1;

#pragma unroll
            for (int j = 0; j < 16; j++) {
                o[j][0] *= corr0; o[j][1] *= corr0;
                o[j][2] *= corr1; o[j][3] *= corr1;
            }

            // ---- O += P @ V ;  P a-frags packed straight from sv ----
            const uint32_t vbase = sb + FOFF_V + s * 17408 + lm_row * FROW_B + lm_chb;
#pragma unroll
            for (int t = 0; t < 4; t++) {
                uint32_t pa[4];
                pa[0] = packh2(sv[2 * t][0],     sv[2 * t][1]);
                pa[1] = packh2(sv[2 * t][2],     sv[2 * t][3]);
                pa[2] = packh2(sv[2 * t + 1][0], sv[2 * t + 1][1]);
                pa[3] = packh2(sv[2 * t + 1][2], sv[2 * t + 1][3]);
                const uint32_t vrow = vbase + t * 16 * FROW_B;
#pragma unroll
                for (int nj = 0; nj < 8; nj++) {
                    uint32_t r0, r1, r2, r3;
                    ldmx4t(r0, r1, r2, r3, vrow + nj * 32);
                    uint32_t bb0[2] = {r0, r1};
                    uint32_t bb1[2] = {r2, r3};
                    mma_f16(o[2 * nj],     pa, bb0);
                    mma_f16(o[2 * nj + 1], pa, bb1);
                }
            }
        }
    }

    // ---- epilogue: normalize, write att [B,S,H] fp16 ----
    {
        const float inv0 = 1.0f / l0;
        const float inv1 = 1.0f / l1;
        __half* dst0 = Out + ((size_t)(b * SS + rg0)) * HH + h * HDD;
        __half* dst1 = Out + ((size_t)(b * SS + rg1)) * HH + h * HDD;
#pragma unroll
        for (int j = 0; j < 16; j++) {
            const int col = j * 8 + (lane & 3) * 2;
            *(__half2*)(dst0 + col) = __floats2half2_rn(o[j][0] * inv0, o[j][1] * inv0);
            *(__half2*)(dst1 + col) = __floats2half2_rn(o[j][2] * inv1, o[j][3] * inv1);
        }
    }
}

// ---------------------------------------------------------------------------
// Launch
// ---------------------------------------------------------------------------
extern "C" void kernel_launch(void* const* d_in, const int* in_sizes, int n_in,
                              void* d_out, int out_size)
{
    const float* hidden = (const float*)d_in[0];
    // d_in[1] = causal_mask: handled analytically
    const float* Wq = (const float*)d_in[2];
    const float* bq = (const float*)d_in[3];
    const float* Wk = (const float*)d_in[4];
    const float* bk = (const float*)d_in[5];
    const float* Wv = (const float*)d_in[6];
    const float* bv = (const float*)d_in[7];
    const float* Wo = (const float*)d_in[8];
    const float* bo = (const float*)d_in[9];
    float* out = (float*)d_out;

    __half *q, *k, *v, *att, *hidt, *wt, *wo;
    cudaGetSymbolAddress((void**)&q,    g_q);
    cudaGetSymbolAddress((void**)&k,    g_k);
    cudaGetSymbolAddress((void**)&v,    g_v);
    cudaGetSymbolAddress((void**)&att,  g_att);
    cudaGetSymbolAddress((void**)&hidt, g_hidt);
    cudaGetSymbolAddress((void**)&wt,   g_wt);
    cudaGetSymbolAddress((void**)&wo,   g_wo);

    // Convert inputs to fp16 (QKV weights into concat layout for fused GEMM)
    const int HN4 = MM * HH / 4;
    const int WN4 = HH * HH / 4;
    cvt_f2h<<<HN4 / 256, 256>>>(hidden, hidt, HN4);
    cvt_f2h<<<WN4 / 256, 256>>>(Wq, wt + 0 * (size_t)HH * HH, WN4);
    cvt_f2h<<<WN4 / 256, 256>>>(Wk, wt + 1 * (size_t)HH * HH, WN4);
    cvt_f2h<<<WN4 / 256, 256>>>(Wv, wt + 2 * (size_t)HH * HH, WN4);
    cvt_f2h<<<WN4 / 256, 256>>>(Wo, wo, WN4);

    cudaFuncSetAttribute(gemm_qkv96, cudaFuncAttributeMaxDynamicSharedMemorySize,
                         QKV_SMEM);
    cudaFuncSetAttribute(gemm_proj, cudaFuncAttributeMaxDynamicSharedMemorySize,
                         GEMM_SMEM);
    cudaFuncSetAttribute(flash_attn_f16, cudaFuncAttributeMaxDynamicSharedMemorySize,
                         FLASH_SMEM);

    // Fused QKV projection: N-tile 96 -> 64x32 = 2048 CTAs (7 waves, 98.9%)
    gemm_qkv96<<<dim3(64, MM / 128), 256, QKV_SMEM>>>(
        hidt, wt, bq, bk, bv, q, k, v);

    // FA2 flash attention (128 q-rows/CTA, register softmax, Q pre-scaled)
    flash_attn_f16<<<dim3(16, NHH, BB), 256, FLASH_SMEM>>>(q, k, v, att);

    // Output projection (fp32 result)
    gemm_proj<<<dim3(16, MM / 128), 256, GEMM_SMEM>>>(att, wo, bo, out);
}